// round 5
// baseline (speedup 1.0000x reference)
#include <cuda_runtime.h>
#include <cstdint>

// ---------------------------------------------------------------------------
// LocalGate: N=131072 tokens, D=1024, E=64, K=2, GATE_ST.
// Outputs (float32, concatenated):
//   [0,262144) token_ordering | [262144,524288) reversed_ordering
//   [524288,786432) cw (==1.0) | [786432,786496) input_splits
//   [786496,9175104) probs [N,64]
// GEMM numerics: replicate XLA:CPU / Eigen gebp fp32 order:
//   logit = fl( chain_fp32(k=0..511) + chain_fp32(k=512..1023) )
// (kc=512 panel split; each panel an ascending FMA chain from zero).
// ---------------------------------------------------------------------------

#define NTOK      131072
#define MDIM      1024
#define NEXP      64
#define NK        (NTOK * 2)

#define TM        128      // tokens per block
#define KC        16       // k-chunk
#define NCHUNK    (MDIM / KC)
#define HALF_CH   (NCHUNK / 2)   // chunks per Eigen panel (512 k / 16)
#define AS        132      // smem A row stride (128 + 4 pad, keeps 16B align)
#define BS        68       // smem B row stride (64 + 4 pad)

#define SORT_BLOCKS 128
#define SORT_CHUNK  (NK / SORT_BLOCKS)   // 2048

__device__ unsigned char g_flat[NK];
__device__ int           g_bh[SORT_BLOCKS * NEXP];
__device__ int           g_start[NEXP];

// packed fp32 FMA: 2 IEEE-rn FMAs per instruction (per-lane identical to FFMA)
__device__ __forceinline__ void ffma2(float2& d, float2 a, float2 b) {
    asm("fma.rn.f32x2 %0, %1, %2, %0;"
        : "+l"(*reinterpret_cast<unsigned long long*>(&d))
        : "l"(*reinterpret_cast<unsigned long long*>(&a)),
          "l"(*reinterpret_cast<unsigned long long*>(&b)));
}

__global__ void __launch_bounds__(256)
gate_kernel(const float* __restrict__ X, const float* __restrict__ W,
            float* __restrict__ probs_out)
{
    __shared__ __align__(16) union SM {
        struct { float A[2][KC * AS]; float B[2][KC * BS]; } g;
        struct { float L[TM * 65]; float inv[TM]; } e;
    } sm;

    const int t    = threadIdx.x;
    const int tok0 = blockIdx.x * TM;
    const int tx   = t & 15;     // token group (8 tokens)
    const int ty   = t >> 4;     // expert group (4 experts)

    const int lr  = t >> 2;      // 0..63
    const int lk4 = t & 3;       // 0..3
    const float* xr0 = X + (size_t)(tok0 + lr) * MDIM + lk4 * 4;
    const float* xr1 = X + (size_t)(tok0 + 64 + lr) * MDIM + lk4 * 4;
    const float* wr  = W + (size_t)lr * MDIM + lk4 * 4;
    const int oA = (lk4 * 4) * AS + lr;
    const int oB = (lk4 * 4) * BS + lr;

    // two Eigen panels: accL covers k in [0,512), accH covers [512,1024)
    float2 accL[4][4], accH[4][4];
    #pragma unroll
    for (int p = 0; p < 4; ++p)
        #pragma unroll
        for (int j = 0; j < 4; ++j) {
            accL[p][j] = make_float2(0.f, 0.f);
            accH[p][j] = make_float2(0.f, 0.f);
        }

    // prefetch chunk 0
    float4 na0 = *(const float4*)(xr0);
    float4 na1 = *(const float4*)(xr1);
    float4 nb  = *(const float4*)(wr);
    {
        float* A0 = sm.g.A[0]; float* B0 = sm.g.B[0];
        A0[oA + 0*AS] = na0.x; A0[oA + 1*AS] = na0.y; A0[oA + 2*AS] = na0.z; A0[oA + 3*AS] = na0.w;
        A0[oA + 0*AS + 64] = na1.x; A0[oA + 1*AS + 64] = na1.y;
        A0[oA + 2*AS + 64] = na1.z; A0[oA + 3*AS + 64] = na1.w;
        B0[oB + 0*BS] = nb.x; B0[oB + 1*BS] = nb.y; B0[oB + 2*BS] = nb.z; B0[oB + 3*BS] = nb.w;
    }
    __syncthreads();

    for (int c = 0; c < NCHUNK; ++c) {
        const int buf = c & 1;
        const bool pre = (c + 1 < NCHUNK);
        if (pre) {
            const int kc = (c + 1) * KC;
            na0 = *(const float4*)(xr0 + kc);
            na1 = *(const float4*)(xr1 + kc);
            nb  = *(const float4*)(wr  + kc);
        }
        const float* Ab = sm.g.A[buf];
        const float* Bb = sm.g.B[buf];
        float2 (*acc)[4] = (c < HALF_CH) ? accL : accH;
        #pragma unroll
        for (int k = 0; k < KC; ++k) {
            float4 a0 = *(const float4*)(Ab + k * AS + tx * 8);
            float4 a1 = *(const float4*)(Ab + k * AS + tx * 8 + 4);
            float4 b  = *(const float4*)(Bb + k * BS + ty * 4);
            float2 ap[4] = { make_float2(a0.x, a0.y), make_float2(a0.z, a0.w),
                             make_float2(a1.x, a1.y), make_float2(a1.z, a1.w) };
            float2 bp[4] = { make_float2(b.x, b.x), make_float2(b.y, b.y),
                             make_float2(b.z, b.z), make_float2(b.w, b.w) };
            #pragma unroll
            for (int p = 0; p < 4; ++p)
                #pragma unroll
                for (int j = 0; j < 4; ++j)
                    ffma2(acc[p][j], ap[p], bp[j]);
        }
        if (pre) {
            float* An = sm.g.A[buf ^ 1]; float* Bn = sm.g.B[buf ^ 1];
            An[oA + 0*AS] = na0.x; An[oA + 1*AS] = na0.y; An[oA + 2*AS] = na0.z; An[oA + 3*AS] = na0.w;
            An[oA + 0*AS + 64] = na1.x; An[oA + 1*AS + 64] = na1.y;
            An[oA + 2*AS + 64] = na1.z; An[oA + 3*AS + 64] = na1.w;
            Bn[oB + 0*BS] = nb.x; Bn[oB + 1*BS] = nb.y; Bn[oB + 2*BS] = nb.z; Bn[oB + 3*BS] = nb.w;
        }
        __syncthreads();
    }

    // ---- epilogue: logits = panelL + panelH -> smem ----
    #pragma unroll
    for (int p = 0; p < 4; ++p) {
        const int tokA = tx * 8 + p * 2;
        #pragma unroll
        for (int j = 0; j < 4; ++j) {
            const int e = ty * 4 + j;
            sm.e.L[tokA * 65 + e]       = accL[p][j].x + accH[p][j].x;
            sm.e.L[(tokA + 1) * 65 + e] = accL[p][j].y + accH[p][j].y;
        }
    }
    __syncthreads();

    if (t < TM) {
        float* row = &sm.e.L[t * 65];
        float v1 = -1e30f, v2 = -1e30f; int i1 = 0, i2 = 0;
        #pragma unroll
        for (int e = 0; e < NEXP; ++e) {
            float v = row[e];
            if (v > v1)      { v2 = v1; i2 = i1; v1 = v; i1 = e; }
            else if (v > v2) { v2 = v;  i2 = e; }
        }
        g_flat[(size_t)(tok0 + t) * 2]     = (unsigned char)i1;
        g_flat[(size_t)(tok0 + t) * 2 + 1] = (unsigned char)i2;
        float s = 0.f;
        #pragma unroll
        for (int e = 0; e < NEXP; ++e) {
            float ex = __expf(row[e] - v1);
            s += ex;
            row[e] = ex;
        }
        sm.e.inv[t] = 1.0f / s;
    }
    __syncthreads();

    float* pbase = probs_out + (size_t)tok0 * NEXP;
    #pragma unroll
    for (int q = 0; q < (TM * NEXP) / 256; ++q) {
        const int idx = t + q * 256;
        const int r = idx >> 6, cix = idx & 63;
        pbase[idx] = sm.e.L[r * 65 + cix] * sm.e.inv[r];
    }
}

// ---------------------------------------------------------------------------
// Stable counting sort over 64 expert ids
// ---------------------------------------------------------------------------
__global__ void hist_cw_kernel(float* __restrict__ cw_out)
{
    __shared__ int h[NEXP];
    const int t = threadIdx.x;
    if (t < NEXP) h[t] = 0;
    __syncthreads();
    const int base = blockIdx.x * SORT_CHUNK;
    #pragma unroll
    for (int q = 0; q < SORT_CHUNK / 256; ++q) {
        const int i = base + t + q * 256;
        atomicAdd(&h[g_flat[i]], 1);
        cw_out[i] = 1.0f;
    }
    __syncthreads();
    if (t < NEXP) g_bh[blockIdx.x * NEXP + t] = h[t];
}

__global__ void scan_kernel(float* __restrict__ splits_out)
{
    const int e = threadIdx.x;               // 64 threads
    int run = 0;
    for (int b = 0; b < SORT_BLOCKS; ++b) {
        const int v = g_bh[b * NEXP + e];
        g_bh[b * NEXP + e] = run;
        run += v;
    }
    splits_out[e] = (float)run;
    __shared__ int tot[NEXP];
    tot[e] = run;
    __syncthreads();
    if (e == 0) {
        int base = 0;
        for (int x = 0; x < NEXP; ++x) { g_start[x] = base; base += tot[x]; }
    }
}

__global__ void rank_kernel(float* __restrict__ to_out, float* __restrict__ ro_out)
{
    __shared__ int cnt[NEXP];
    const int lane = threadIdx.x;            // 32 threads (one warp, stable order)
    cnt[lane]      = g_start[lane]      + g_bh[blockIdx.x * NEXP + lane];
    cnt[lane + 32] = g_start[lane + 32] + g_bh[blockIdx.x * NEXP + lane + 32];
    __syncwarp();
    const int base = blockIdx.x * SORT_CHUNK;
    for (int it = 0; it < SORT_CHUNK / 32; ++it) {
        const int i = base + it * 32 + lane;
        const int e = g_flat[i];
        const unsigned peers = __match_any_sync(0xffffffffu, e);
        const int leader = __ffs(peers) - 1;
        const int prior  = __popc(peers & ((1u << lane) - 1));
        int b = 0;
        if (lane == leader) b = atomicAdd(&cnt[e], __popc(peers));
        b = __shfl_sync(peers, b, leader);
        const int p = b + prior;
        to_out[p] = (float)(i >> 1);         // dispatch slot -> source token
        ro_out[i] = (float)p;                // flat slot -> rank
    }
}

// ---------------------------------------------------------------------------
extern "C" void kernel_launch(void* const* d_in, const int* in_sizes, int n_in,
                              void* d_out, int out_size)
{
    const float* X = (const float*)d_in[0];   // [131072, 1024]
    const float* W = (const float*)d_in[1];   // [64, 1024]
    float* out = (float*)d_out;

    float* TO  = out;                 // token_ordering
    float* RO  = out + NK;            // reversed_ordering
    float* CW  = out + 2 * NK;        // cw (all 1.0)
    float* SPL = out + 3 * NK;        // input_splits
    float* PR  = out + 3 * NK + NEXP; // probs [N, E]

    gate_kernel<<<NTOK / TM, 256>>>(X, W, PR);
    hist_cw_kernel<<<SORT_BLOCKS, 256>>>(CW);
    scan_kernel<<<1, NEXP>>>(SPL);
    rank_kernel<<<SORT_BLOCKS, 32>>>(TO, RO);
}